// round 6
// baseline (speedup 1.0000x reference)
#include <cuda_runtime.h>

// DepthwiseRREUp: groups=C*G conv_transpose2d, kernel=stride=2, pad=0.
// out[b,c,g, 2i+di, 2j+dj] = x[b,c,g,i,j] * rot90(dw[c], g)[di][dj]
// Pure streaming op: 128 MiB read, 512 MiB write, no reduction.
//
// x:  [B=8, C=256, G=4, H=64, W=64] fp32   (in_sizes[0] = 33,554,432)
// dw: [C=256, 1, 2, 2] fp32               (in_sizes[1] = 1024)
// out:[B, C, G, 128, 128] fp32            (out_size   = 134,217,728)
//
// One thread per input float4 (4 consecutive W positions):
//   1x 16B coalesced load, 4x 16B coalesced stores (2 per output row).

__global__ void __launch_bounds__(256)
DepthwiseRREUp_40106404610493_kernel(const float4* __restrict__ x4,
                                     const float4* __restrict__ dw4,   // [C] of (a,b,c,d)
                                     float4* __restrict__ out4,
                                     int total4) {
    int idx = blockIdx.x * blockDim.x + threadIdx.x;
    if (idx >= total4) return;

    // Input plane (H*W = 4096 floats = 1024 float4) decomposition.
    int j4 = idx & 15;            // which float4 within the 64-wide row (16 per row)
    int i  = (idx >> 4) & 63;     // input row
    int g  = (idx >> 10) & 3;     // rotation index (warp-uniform)
    int c  = (idx >> 12) & 255;   // channel
    int plane = idx >> 10;        // linear (b,c,g) plane index

    float4 xv = x4[idx];
    float4 w  = dw4[c];           // a=w.x b=w.y c=w.z d=w.w  (row-major 2x2)

    // numpy rot90 (CCW) k=g of [[a,b],[c,d]]:
    //   g=0: a b / c d    g=1: b d / a c
    //   g=2: d c / b a    g=3: c a / d b
    float f00, f01, f10, f11;
    switch (g) {
        case 0:  f00 = w.x; f01 = w.y; f10 = w.z; f11 = w.w; break;
        case 1:  f00 = w.y; f01 = w.w; f10 = w.x; f11 = w.z; break;
        case 2:  f00 = w.w; f01 = w.z; f10 = w.y; f11 = w.x; break;
        default: f00 = w.z; f01 = w.x; f10 = w.w; f11 = w.y; break;
    }

    // Output plane = 128*128 floats = 4096 float4; row stride = 32 float4.
    // This thread covers output cols [8*j4, 8*j4+8) on rows 2i and 2i+1.
    int base = plane * 4096 + (2 * i) * 32 + j4 * 2;

    float4 r0a = make_float4(xv.x * f00, xv.x * f01, xv.y * f00, xv.y * f01);
    float4 r0b = make_float4(xv.z * f00, xv.z * f01, xv.w * f00, xv.w * f01);
    float4 r1a = make_float4(xv.x * f10, xv.x * f11, xv.y * f10, xv.y * f11);
    float4 r1b = make_float4(xv.z * f10, xv.z * f11, xv.w * f10, xv.w * f11);

    out4[base]          = r0a;
    out4[base + 1]      = r0b;
    out4[base + 32]     = r1a;
    out4[base + 33]     = r1b;
}

extern "C" void kernel_launch(void* const* d_in, const int* in_sizes, int n_in,
                              void* d_out, int out_size) {
    const float4* x4  = (const float4*)d_in[0];
    const float4* dw4 = (const float4*)d_in[1];   // C channels x 4 floats
    float4* out4      = (float4*)d_out;

    int total4 = in_sizes[0] / 4;                 // 8,388,608
    int threads = 256;
    int blocks = (total4 + threads - 1) / threads;
    DepthwiseRREUp_40106404610493_kernel<<<blocks, threads>>>(x4, dw4, out4, total4);
}